// round 16
// baseline (speedup 1.0000x reference)
#include <cuda_runtime.h>

#define E_TOTAL 1600000
#define N_NODES 50000

#define FSCALE     0.17677669529663687f  // 1/sqrt(32)
#define FINV_SQRT3 0.57735026918962576f  // 1/sqrt(3)

#define SCAN_B   512
#define SCAN_NB  ((N_NODES + SCAN_B - 1) / SCAN_B)   // 98

__device__ int    g_counts[N_NODES];
__device__ int    g_cursor[N_NODES];
__device__ int    g_offsets[N_NODES + 1];
__device__ int    g_scantmp[N_NODES];
__device__ int    g_bsums[SCAN_NB];
__device__ int    g_bbase[SCAN_NB];
__device__ float4 g_rec4[(size_t)E_TOTAL * 4];  // slot -> {h0..3, h4..7, ef, snd<<3}
__device__ float4 g_nodes4[N_NODES * 8];        // node -> 8 x {s_m, v_m0, v_m1, v_m2}

__global__ void k_zero_counts() {
    int i = blockIdx.x * blockDim.x + threadIdx.x;
    if (i < N_NODES) g_counts[i] = 0;
}

// Transpose node_feats rows into per-m float4 {s, v0, v1, v2}
__global__ void k_prep_nodes(const float* __restrict__ node_feats) {
    int i = blockIdx.x * blockDim.x + threadIdx.x;   // node*8 + m
    if (i >= N_NODES * 8) return;
    int node = i >> 3;
    int m    = i & 7;
    const float* nf = node_feats + node * 32;
    g_nodes4[i] = make_float4(__ldg(nf + m),
                              __ldg(nf + 8 + 3 * m),
                              __ldg(nf + 9 + 3 * m),
                              __ldg(nf + 10 + 3 * m));
}

__global__ void k_count(const int* __restrict__ receivers) {
    int e = blockIdx.x * blockDim.x + threadIdx.x;
    if (e < E_TOTAL) atomicAdd(&g_counts[__ldg(&receivers[e])], 1);
}

// Pass 1: per-block inclusive scan of counts
__global__ __launch_bounds__(SCAN_B) void k_scan1() {
    __shared__ int sh[SCAN_B];
    int t   = threadIdx.x;
    int idx = blockIdx.x * SCAN_B + t;
    int v   = (idx < N_NODES) ? g_counts[idx] : 0;
    sh[t] = v;
    __syncthreads();
    for (int off = 1; off < SCAN_B; off <<= 1) {
        int u = (t >= off) ? sh[t - off] : 0;
        __syncthreads();
        sh[t] += u;
        __syncthreads();
    }
    if (idx < N_NODES) g_scantmp[idx] = sh[t];
    if (t == SCAN_B - 1) g_bsums[blockIdx.x] = sh[t];
}

// Pass 2: single small block scans the 98 block sums -> exclusive bases
__global__ __launch_bounds__(128) void k_scan2() {
    __shared__ int sh[128];
    int t = threadIdx.x;
    int v = (t < SCAN_NB) ? g_bsums[t] : 0;
    sh[t] = v;
    __syncthreads();
    for (int off = 1; off < 128; off <<= 1) {
        int u = (t >= off) ? sh[t - off] : 0;
        __syncthreads();
        sh[t] += u;
        __syncthreads();
    }
    if (t < SCAN_NB) g_bbase[t] = sh[t] - v;   // exclusive base
    if (t == SCAN_NB - 1) g_offsets[N_NODES] = sh[t];
}

// Pass 3: global exclusive offsets + cursor
__global__ __launch_bounds__(SCAN_B) void k_scan3() {
    int idx = blockIdx.x * SCAN_B + threadIdx.x;
    if (idx < N_NODES) {
        int off = g_bbase[blockIdx.x] + g_scantmp[idx] - g_counts[idx];
        g_offsets[idx] = off;
        g_cursor[idx]  = off;
    }
}

// Fused fill + hidden MLP: coalesced reads in edge order; one aligned 64B
// record write per edge.
__global__ __launch_bounds__(256) void k_fill_hidden(
    const int*    __restrict__ senders,
    const int*    __restrict__ receivers,
    const float4* __restrict__ radial,
    const float4* __restrict__ edge_features,
    const float*  __restrict__ w1)
{
    __shared__ float sw1[64];
    int t = threadIdx.x;
    if (t < 64) sw1[t] = w1[t];
    __syncthreads();

    int e = blockIdx.x * 256 + t;
    if (e >= E_TOTAL) return;

    float4 r0 = __ldg(&radial[2 * e]);
    float4 r1 = __ldg(&radial[2 * e + 1]);
    float4 ef = __ldg(&edge_features[e]);
    int   snd = __ldg(&senders[e]);
    int   rcv = __ldg(&receivers[e]);

    float r[8] = {r0.x, r0.y, r0.z, r0.w, r1.x, r1.y, r1.z, r1.w};
    float h[8];
    #pragma unroll
    for (int j = 0; j < 8; j++) {
        float acc = 0.f;
        #pragma unroll
        for (int i = 0; i < 8; i++) acc = fmaf(r[i], sw1[i * 8 + j], acc);
        h[j] = acc * (FSCALE / (1.f + __expf(-acc)));
    }

    int pos = atomicAdd(&g_cursor[rcv], 1);
    size_t base = (size_t)pos << 2;
    g_rec4[base]     = make_float4(h[0], h[1], h[2], h[3]);
    g_rec4[base + 1] = make_float4(h[4], h[5], h[6], h[7]);
    g_rec4[base + 2] = ef;
    g_rec4[base + 3] = make_float4(__int_as_float(snd << 3), 0.f, 0.f, 0.f);
}

// Compute for one edge given prefetched record + node data
#define EDGE_COMPUTE(H0, H1, EF, ND)                                          \
    {                                                                         \
        float s = (ND).x, v0 = (ND).y, v1 = (ND).z, v2 = (ND).w;              \
        float e0 = (EF).x, e1x = (EF).y, e1y = (EF).z, e1z = (EF).w;          \
        float wa, wb;                                                         \
        wa = fmaf((H0).x, w2A[0], fmaf((H0).y, w2A[1],                        \
             fmaf((H0).z, w2A[2], (H0).w * w2A[3])));                         \
        wa = fmaf((H1).x, w2A[4], fmaf((H1).y, w2A[5],                        \
             fmaf((H1).z, w2A[6], fmaf((H1).w, w2A[7], wa))));                \
        wb = fmaf((H0).x, w2B[0], fmaf((H0).y, w2B[1],                        \
             fmaf((H0).z, w2B[2], (H0).w * w2B[3])));                         \
        wb = fmaf((H1).x, w2B[4], fmaf((H1).y, w2B[5],                        \
             fmaf((H1).z, w2B[6], fmaf((H1).w, w2B[7], wb))));                \
        float eS = fmaf(mg1, e0, mg0);                                        \
        float fV = fmaf(mg2, e0, mg0);                                        \
        float dot = fmaf(v0, e1x, fmaf(v1, e1y, v2 * e1z));                   \
        float scal_inner = fmaf(s, eS, dot * mg2);                            \
        float sfs = s * mg1;                                                  \
        float i0 = fmaf(v0, fV, sfs * e1x);                                   \
        float i1 = fmaf(v1, fV, sfs * e1y);                                   \
        float i2 = fmaf(v2, fV, sfs * e1z);                                   \
        acc_s  = fmaf(scal_inner, wa, acc_s);                                 \
        acc_v0 = fmaf(i0, wb, acc_v0);                                        \
        acc_v1 = fmaf(i1, wb, acc_v1);                                        \
        acc_v2 = fmaf(i2, wb, acc_v2);                                        \
    }

// One block (4 warps) per node; warp takes 1/4 of segment.
// Main loop: 4 edges per iteration, all record loads batched up front.
__global__ __launch_bounds__(128) void k_gather(
    const float* __restrict__ w2,
    float*       __restrict__ out)
{
    __shared__ float red[4][96];

    int node = blockIdx.x;
    int lane = threadIdx.x & 31;
    int wi   = threadIdx.x >> 5;
    int mm   = lane & 7;

    bool g0 = lane < 8;
    bool g1 = (lane >= 8) && (lane < 16);
    bool g2 = (lane >= 16) && (lane < 24);
    int  cA = (lane < 24) ? lane : 0;
    float mg0 = g0 ? 1.f : 0.f;
    float mg1 = g1 ? 1.f : 0.f;
    float mg2 = g2 ? 1.f : 0.f;
    float sA  = g2 ? FINV_SQRT3 : 1.f;

    float w2A[8], w2B[8];
    #pragma unroll
    for (int j = 0; j < 8; j++) {
        w2A[j] = __ldg(&w2[j * 48 + cA]) * sA;
        w2B[j] = __ldg(&w2[j * 48 + 24 + cA]);
    }

    int beg = g_offsets[node];
    int end = g_offsets[node + 1];
    int len = end - beg;
    int lo  = beg + (len * wi)       / 4;
    int hi  = beg + (len * (wi + 1)) / 4;

    float acc_s = 0.f, acc_v0 = 0.f, acc_v1 = 0.f, acc_v2 = 0.f;

    int k = lo;
    #pragma unroll 1
    for (; k + 4 <= hi; k += 4) {
        float4 ha[4], hb[4], ec[4];
        int    sb[4];
        #pragma unroll
        for (int u = 0; u < 4; u++) {
            const float4* rp = g_rec4 + ((size_t)(k + u) << 2);
            ha[u] = rp[0];
            hb[u] = rp[1];
            ec[u] = rp[2];
            sb[u] = __float_as_int(rp[3].x);
        }
        float4 nd[4];
        #pragma unroll
        for (int u = 0; u < 4; u++) nd[u] = g_nodes4[sb[u] + mm];
        #pragma unroll
        for (int u = 0; u < 4; u++) EDGE_COMPUTE(ha[u], hb[u], ec[u], nd[u])
    }
    #pragma unroll 1
    for (; k < hi; k++) {
        const float4* rp = g_rec4 + ((size_t)k << 2);
        float4 ha = rp[0];
        float4 hb = rp[1];
        float4 ec = rp[2];
        int    sb = __float_as_int(rp[3].x);
        float4 nd = g_nodes4[sb + mm];
        EDGE_COMPUTE(ha, hb, ec, nd)
    }

    if (lane < 24) {
        red[wi][lane]              = acc_s;
        red[wi][24 + 3 * lane]     = acc_v0;
        red[wi][24 + 3 * lane + 1] = acc_v1;
        red[wi][24 + 3 * lane + 2] = acc_v2;
    }
    __syncthreads();

    int t = threadIdx.x;
    if (t < 96) {
        out[(size_t)node * 96 + t] = red[0][t] + red[1][t] + red[2][t] + red[3][t];
    }
}

extern "C" void kernel_launch(void* const* d_in, const int* in_sizes, int n_in,
                              void* d_out, int out_size) {
    const float*  node_feats    = (const float*)d_in[0];
    const float4* edge_features = (const float4*)d_in[1];
    const float4* radial        = (const float4*)d_in[2];
    const float*  w1            = (const float*)d_in[3];
    const float*  w2            = (const float*)d_in[4];
    const int*    senders       = (const int*)d_in[5];
    const int*    receivers     = (const int*)d_in[6];
    float* out = (float*)d_out;

    k_zero_counts<<<(N_NODES + 511) / 512, 512>>>();
    k_prep_nodes<<<(N_NODES * 8 + 255) / 256, 256>>>(node_feats);
    k_count<<<(E_TOTAL + 511) / 512, 512>>>(receivers);
    k_scan1<<<SCAN_NB, SCAN_B>>>();
    k_scan2<<<1, 128>>>();
    k_scan3<<<SCAN_NB, SCAN_B>>>();
    k_fill_hidden<<<(E_TOTAL + 255) / 256, 256>>>(senders, receivers, radial,
                                                  edge_features, w1);
    k_gather<<<N_NODES, 128>>>(w2, out);
}